// round 14
// baseline (speedup 1.0000x reference)
#include <cuda_runtime.h>
#include <cstdint>

// DSQN forward: B=512, T=1024, F=128, H=128, A=16. Faithful fp32.
//
// Numerics contract (verified rel_err 5.5e-9):
//   cur1 = sequential-k FMA dot (acc 0) THEN + b1
//   mem  = ((clip(beta)*mem) + cur) - reset            (3 separate roundings)
//   cur2 = ascending-h1 sum of W2^T cols THEN + b2
//   out  = sum of W3 cols THEN + b3  (order permuted: output-only rounding)
//
// R14 = R13 kernels + 2-chunk overlap (256 batches/chunk):
//   prep -> gemm(c0) -> { gemm(c1) on stream0  ||  lif1/cur2/lif2out(c0) on
//   side stream } -> lif1/cur2/lif2out(c1).
//   R12's failure was 8 small chunks serializing latency-bound side chains;
//   2 big chunks keep side grids large (side ~135us < gemm-half ~232us).

#define T_STEPS 1024
#define F_DIM   128
#define H_DIM   128
#define A_DIM   16
#define B_TOT   512
#define M_TOT   (B_TOT * T_STEPS)      // 524288
#define B_CHUNK 256
#define M_CHUNK (B_CHUNK * T_STEPS)

__device__ float g_cur1[M_TOT * H_DIM];            // 268 MB
__device__ float g_cur2[M_TOT * H_DIM];            // 268 MB (permuted h2: p)
__device__ float g_W1T[F_DIM * H_DIM];             // [k][n]
__device__ float g_W2p[H_DIM * H_DIM];             // [h1][(h2&31)*4+(h2>>5)]
__device__ float g_W3p[H_DIM * A_DIM];             // [p][a], h2(p)=(p>>2)+32*(p&3)
__device__ uint4 g_m1[M_TOT];                      // spk1 masks per (b,t)

// ---------------- prep: weight layouts ----------------
__global__ void prep_kernel(const float* __restrict__ W1,
                            const float* __restrict__ W2,
                            const float* __restrict__ W3)
{
    int i = threadIdx.x + blockIdx.x * blockDim.x;
    if (i < H_DIM * F_DIM) {
        int n = i >> 7, k = i & 127;
        g_W1T[k * H_DIM + n] = W1[i];
        int h2 = n, h1 = k;
        g_W2p[h1 * H_DIM + (h2 & 31) * 4 + (h2 >> 5)] = W2[i];
    }
    if (i < H_DIM * A_DIM) {
        int p = i >> 4, a = i & 15;
        int h2 = (p >> 2) + 32 * (p & 3);
        g_W3p[p * A_DIM + a] = W3[a * H_DIM + h2];
    }
}

// ---------------- gemm: cur1 = X @ W1^T + b1 (R13 version + mbase) ----------
#define GM_M      64
#define GM_THR    128
#define XS_STRIDE 132
#define GEMM_SMEM ((F_DIM * H_DIM + GM_M * XS_STRIDE) * 4)   // 97.3 KB

__global__ __launch_bounds__(GM_THR, 2)
void gemm_kernel(const float* __restrict__ state, const float* __restrict__ b1,
                 int mbase)
{
    extern __shared__ float sg[];
    float* w1t_s = sg;                          // [k][n] 128x128
    float* x_s   = sg + F_DIM * H_DIM;          // [m][k] 64x132

    const int tid  = threadIdx.x;
    const int lane = tid & 31;
    const int wrp  = tid >> 5;                  // 0..3
    const int m0   = mbase + blockIdx.x * GM_M;
    const int n0   = wrp * 32;

    #pragma unroll 8
    for (int i = tid; i < (F_DIM * H_DIM) / 4; i += GM_THR)
        reinterpret_cast<float4*>(w1t_s)[i] =
            reinterpret_cast<const float4*>(g_W1T)[i];
    #pragma unroll 4
    for (int i = tid; i < GM_M * 32; i += GM_THR) {
        int m = i >> 5, k4 = i & 31;
        float4 v = reinterpret_cast<const float4*>(state)[(size_t)(m0 + m) * 32 + k4];
        *reinterpret_cast<float4*>(&x_s[m * XS_STRIDE + 4 * k4]) = v;
    }
    __syncthreads();

    unsigned long long A0[16], A1[16];
    #pragma unroll
    for (int p = 0; p < 16; ++p) { A0[p] = 0ull; A1[p] = 0ull; }

    const float* xr0 = &x_s[lane * XS_STRIDE];
    const float* xr1 = &x_s[(lane + 32) * XS_STRIDE];

    #pragma unroll 2
    for (int k = 0; k < F_DIM; k += 4) {
        float4 xa = *reinterpret_cast<const float4*>(&xr0[k]);
        float4 xb = *reinterpret_cast<const float4*>(&xr1[k]);
        float xav[4] = {xa.x, xa.y, xa.z, xa.w};
        float xbv[4] = {xb.x, xb.y, xb.z, xb.w};
        #pragma unroll
        for (int j = 0; j < 4; ++j) {
            unsigned long long px0, px1;
            asm("mov.b64 %0, {%1, %1};" : "=l"(px0) : "f"(xav[j]));
            asm("mov.b64 %0, {%1, %1};" : "=l"(px1) : "f"(xbv[j]));
            const ulonglong2* wp =
                reinterpret_cast<const ulonglong2*>(&w1t_s[(k + j) * H_DIM + n0]);
            #pragma unroll
            for (int q = 0; q < 8; ++q) {
                ulonglong2 w2 = wp[q];
                asm("fma.rn.f32x2 %0, %1, %2, %0;" : "+l"(A0[2*q  ]) : "l"(px0), "l"(w2.x));
                asm("fma.rn.f32x2 %0, %1, %2, %0;" : "+l"(A0[2*q+1]) : "l"(px0), "l"(w2.y));
                asm("fma.rn.f32x2 %0, %1, %2, %0;" : "+l"(A1[2*q  ]) : "l"(px1), "l"(w2.x));
                asm("fma.rn.f32x2 %0, %1, %2, %0;" : "+l"(A1[2*q+1]) : "l"(px1), "l"(w2.y));
            }
        }
    }

    float bn[32];
    #pragma unroll
    for (int j = 0; j < 32; ++j) bn[j] = b1[n0 + j];

    #pragma unroll
    for (int mi = 0; mi < 2; ++mi) {
        const unsigned long long* ap = mi ? A1 : A0;
        size_t mg = (size_t)(m0 + lane + 32 * mi);
        #pragma unroll
        for (int q2 = 0; q2 < 8; ++q2) {
            float f0, f1, f2, f3;
            asm("mov.b64 {%0, %1}, %2;" : "=f"(f0), "=f"(f1) : "l"(ap[2*q2]));
            asm("mov.b64 {%0, %1}, %2;" : "=f"(f2), "=f"(f3) : "l"(ap[2*q2+1]));
            float4 o;
            o.x = __fadd_rn(f0, bn[4*q2+0]);
            o.y = __fadd_rn(f1, bn[4*q2+1]);
            o.z = __fadd_rn(f2, bn[4*q2+2]);
            o.w = __fadd_rn(f3, bn[4*q2+3]);
            reinterpret_cast<float4*>(g_cur1)[mg * 32 + (n0 >> 2) + q2] = o;
        }
    }
}

// ---------------- lif1: scalar scans -> masks1 (chunk) ----------------
__global__ __launch_bounds__(256, 4)
void lif1_kernel(const float* __restrict__ hidden, const float* __restrict__ beta1,
                 int b0)
{
    const int lane = threadIdx.x & 31;
    const int wg   = blockIdx.x * 8 + (threadIdx.x >> 5);
    const int b    = b0 + (wg >> 2), g = wg & 3;
    const int h    = g * 32 + lane;

    const float beta = fminf(fmaxf(beta1[h], 0.0f), 1.0f);
    float mem = hidden[(size_t)b * 2 * H_DIM + h];
    const float* cb = g_cur1 + (size_t)b * T_STEPS * H_DIM + h;
    unsigned* mout = reinterpret_cast<unsigned*>(g_m1) + (size_t)b * T_STEPS * 4 + g;

    float cur[8], nxt[8];
    #pragma unroll
    for (int i = 0; i < 8; ++i) cur[i] = cb[(size_t)i * H_DIM];

    for (int t0 = 0; t0 < T_STEPS; t0 += 8) {
        if (t0 + 8 < T_STEPS) {
            #pragma unroll
            for (int i = 0; i < 8; ++i) nxt[i] = cb[(size_t)(t0 + 8 + i) * H_DIM];
        }
        #pragma unroll
        for (int u = 0; u < 8; ++u) {
            float reset = (mem > 1.0f) ? 1.0f : 0.0f;
            float m = __fsub_rn(__fadd_rn(__fmul_rn(beta, mem), cur[u]), reset);
            mem = m;
            unsigned msk = __ballot_sync(0xFFFFFFFFu, m > 1.0f);
            if (lane == 0) mout[(size_t)(t0 + u) * 4] = msk;
        }
        #pragma unroll
        for (int i = 0; i < 8; ++i) cur[i] = nxt[i];
    }
}

// ---------------- cur2: sparse gather per (b,t) (chunk) ----------------
#define C2_SMEM (H_DIM * H_DIM * 4)   // 64 KB

__global__ __launch_bounds__(256, 3)
void cur2_kernel(const float* __restrict__ b2, int b0)
{
    extern __shared__ float w2s[];
    const int tid  = threadIdx.x;
    const int lane = tid & 31;

    #pragma unroll 4
    for (int i = tid; i < (H_DIM * H_DIM) / 4; i += 256)
        reinterpret_cast<float4*>(w2s)[i] =
            reinterpret_cast<const float4*>(g_W2p)[i];

    float b2j[4];
    #pragma unroll
    for (int j = 0; j < 4; ++j) b2j[j] = b2[lane + 32 * j];
    __syncthreads();

    const int W  = blockIdx.x * 8 + (tid >> 5);
    const int b  = b0 + (W >> 6);
    const int t0 = (W & 63) * 16;
    const size_t base = (size_t)b * T_STEPS + t0;

    uint4 mk = g_m1[base];
    #pragma unroll 2
    for (int tt = 0; tt < 16; ++tt) {
        uint4 nk = (tt + 1 < 16) ? g_m1[base + tt + 1] : make_uint4(0u,0u,0u,0u);

        float c0 = 0.f, c1 = 0.f, c2 = 0.f, c3 = 0.f;
        unsigned mw[4] = {mk.x, mk.y, mk.z, mk.w};
        #pragma unroll
        for (int kw = 0; kw < 4; ++kw) {
            unsigned m = mw[kw];
            while (m) {
                int j = __ffs(m) - 1;
                m &= m - 1;
                float4 v = *reinterpret_cast<const float4*>(
                    &w2s[(kw * 32 + j) * H_DIM + lane * 4]);
                c0 = __fadd_rn(c0, v.x);
                c1 = __fadd_rn(c1, v.y);
                c2 = __fadd_rn(c2, v.z);
                c3 = __fadd_rn(c3, v.w);
            }
        }
        float4 o;
        o.x = __fadd_rn(c0, b2j[0]);
        o.y = __fadd_rn(c1, b2j[1]);
        o.z = __fadd_rn(c2, b2j[2]);
        o.w = __fadd_rn(c3, b2j[3]);
        reinterpret_cast<float4*>(g_cur2)[(base + tt) * 32 + lane] = o;
        mk = nk;
    }
}

// ---------------- lif2 + out fused (chunk) ----------------
__global__ __launch_bounds__(256, 2)
void lif2out_kernel(const float* __restrict__ hidden,
                    const float* __restrict__ beta2,
                    const float* __restrict__ b3,
                    float* __restrict__ out, int b0)
{
    __shared__ uint4 msks[2 * T_STEPS];        // 32 KB
    __shared__ float w3s[H_DIM * A_DIM];       // 8 KB

    const int tid  = threadIdx.x;
    const int lane = tid & 31;
    const int wid  = tid >> 5;                 // 0..7

    for (int i = tid; i < H_DIM * A_DIM; i += 256) w3s[i] = g_W3p[i];

    // ---- scan phase: warp = (b_local, quarter w) ----
    const int bl = wid >> 2, w = wid & 3;
    const int b  = b0 + blockIdx.x * 2 + bl;
    const int p  = w * 32 + lane;
    const int h2 = (p >> 2) + 32 * (p & 3);

    const float beta = fminf(fmaxf(beta2[h2], 0.0f), 1.0f);
    float mem = hidden[(size_t)b * 2 * H_DIM + H_DIM + h2];
    const float* cb = g_cur2 + (size_t)b * T_STEPS * H_DIM + p;
    unsigned* mout = reinterpret_cast<unsigned*>(msks) + (size_t)bl * T_STEPS * 4 + w;

    float cur[8], nxt[8];
    #pragma unroll
    for (int i = 0; i < 8; ++i) cur[i] = cb[(size_t)i * H_DIM];

    for (int t0 = 0; t0 < T_STEPS; t0 += 8) {
        if (t0 + 8 < T_STEPS) {
            #pragma unroll
            for (int i = 0; i < 8; ++i) nxt[i] = cb[(size_t)(t0 + 8 + i) * H_DIM];
        }
        #pragma unroll
        for (int u = 0; u < 8; ++u) {
            float reset = (mem > 1.0f) ? 1.0f : 0.0f;
            float m = __fsub_rn(__fadd_rn(__fmul_rn(beta, mem), cur[u]), reset);
            mem = m;
            unsigned msk = __ballot_sync(0xFFFFFFFFu, m > 1.0f);
            if (lane == 0) mout[(t0 + u) * 4] = msk;
        }
        #pragma unroll
        for (int i = 0; i < 8; ++i) cur[i] = nxt[i];
    }

    __syncthreads();

    // ---- out phase ----
    const int a = lane & 15;
    const float b3a = b3[a];

    for (int pass = 0; pass < 128; ++pass) {
        const int task = pass * 16 + wid * 2 + (lane >> 4);
        const int tb = task >> 10;
        const int tt = task & 1023;

        uint4 mk = msks[tb * T_STEPS + tt];
        float o = 0.f;
        unsigned mw[4] = {mk.x, mk.y, mk.z, mk.w};
        #pragma unroll
        for (int kw = 0; kw < 4; ++kw) {
            unsigned m = mw[kw];
            while (m) {
                int j = __ffs(m) - 1;
                m &= m - 1;
                o = __fadd_rn(o, w3s[(kw * 32 + j) * A_DIM + a]);
            }
        }
        o = __fadd_rn(o, b3a);
        out[((size_t)(b0 + blockIdx.x * 2 + tb) * T_STEPS + tt) * A_DIM + a] = o;
    }
}

extern "C" void kernel_launch(void* const* d_in, const int* in_sizes, int n_in,
                              void* d_out, int out_size) {
    const float* state  = (const float*)d_in[0];  // [512,1024,128]
    const float* hidden = (const float*)d_in[1];  // [512,1,2,128]
    const float* W1     = (const float*)d_in[2];
    const float* b1     = (const float*)d_in[3];
    const float* beta1  = (const float*)d_in[4];
    const float* W2     = (const float*)d_in[5];
    const float* b2     = (const float*)d_in[6];
    const float* beta2  = (const float*)d_in[7];
    const float* W3     = (const float*)d_in[8];
    const float* b3     = (const float*)d_in[9];
    float* out = (float*)d_out;                   // [512,1024,16]

    cudaFuncSetAttribute(gemm_kernel,
                         cudaFuncAttributeMaxDynamicSharedMemorySize, GEMM_SMEM);
    cudaFuncSetAttribute(cur2_kernel,
                         cudaFuncAttributeMaxDynamicSharedMemorySize, C2_SMEM);

    static cudaStream_t side = nullptr;
    static cudaEvent_t ev_g0 = nullptr, ev_done = nullptr;
    if (!side) {
        cudaStreamCreateWithFlags(&side, cudaStreamNonBlocking);
        cudaEventCreateWithFlags(&ev_g0, cudaEventDisableTiming);
        cudaEventCreateWithFlags(&ev_done, cudaEventDisableTiming);
    }

    prep_kernel<<<64, 256>>>(W1, W2, W3);

    // chunk 0 gemm on main stream
    gemm_kernel<<<M_CHUNK / GM_M, GM_THR, GEMM_SMEM>>>(state, b1, 0);
    cudaEventRecord(ev_g0, 0);

    // chunk 1 gemm on main stream (overlaps with side chain of chunk 0)
    gemm_kernel<<<M_CHUNK / GM_M, GM_THR, GEMM_SMEM>>>(state, b1, M_CHUNK);

    // side chain chunk 0 (after chunk-0 gemm)
    cudaStreamWaitEvent(side, ev_g0, 0);
    lif1_kernel<<<B_CHUNK * 4 / 8, 256, 0, side>>>(hidden, beta1, 0);
    cur2_kernel<<<B_CHUNK * 64 / 8, 256, C2_SMEM, side>>>(b2, 0);
    lif2out_kernel<<<B_CHUNK / 2, 256, 0, side>>>(hidden, beta2, b3, out, 0);
    cudaEventRecord(ev_done, side);

    // side chain chunk 1 on main stream (after gemm c1, and after side c0 so
    // the latency-bound scans are not contended)
    cudaStreamWaitEvent(0, ev_done, 0);
    lif1_kernel<<<B_CHUNK * 4 / 8, 256>>>(hidden, beta1, B_CHUNK);
    cur2_kernel<<<B_CHUNK * 64 / 8, 256, C2_SMEM>>>(b2, B_CHUNK);
    lif2out_kernel<<<B_CHUNK / 2, 256>>>(hidden, beta2, b3, out, B_CHUNK);
}

// round 15
// speedup vs baseline: 1.4039x; 1.4039x over previous
#include <cuda_runtime.h>
#include <cstdint>

// DSQN forward: B=512, T=1024, F=128, H=128, A=16. Faithful fp32.
//
// Numerics contract (verified rel_err 5.5e-9):
//   cur1 = sequential-k FMA dot (acc 0) THEN + b1
//   mem  = ((clip(beta)*mem) + cur) - reset            (3 separate roundings)
//   cur2 = ascending-h1 sum of W2^T cols THEN + b2
//   out  = sum of W3 cols THEN + b3  (order permuted: output-only rounding)
//
// R15 = R13 single-stream pipeline (overlap attempts R12/R14 both regressed:
// latency-bound scans don't shrink with batch chunking) + depth-4 register
// prefetch pipelines in lif1 and lif2out's scan phase (R14 ncu: lif1 at
// issue=15%, one-block-ahead prefetch covered ~15% of DRAM latency).

#define T_STEPS 1024
#define F_DIM   128
#define H_DIM   128
#define A_DIM   16
#define B_TOT   512
#define M_TOT   (B_TOT * T_STEPS)      // 524288

__device__ float g_cur1[M_TOT * H_DIM];            // 268 MB
__device__ float g_cur2[M_TOT * H_DIM];            // 268 MB (permuted h2: p)
__device__ float g_W1T[F_DIM * H_DIM];             // [k][n]
__device__ float g_W2p[H_DIM * H_DIM];             // [h1][(h2&31)*4+(h2>>5)]
__device__ float g_W3p[H_DIM * A_DIM];             // [p][a], h2(p)=(p>>2)+32*(p&3)
__device__ uint4 g_m1[M_TOT];                      // spk1 masks per (b,t)

// ---------------- prep: weight layouts ----------------
__global__ void prep_kernel(const float* __restrict__ W1,
                            const float* __restrict__ W2,
                            const float* __restrict__ W3)
{
    int i = threadIdx.x + blockIdx.x * blockDim.x;
    if (i < H_DIM * F_DIM) {
        int n = i >> 7, k = i & 127;
        g_W1T[k * H_DIM + n] = W1[i];
        int h2 = n, h1 = k;
        g_W2p[h1 * H_DIM + (h2 & 31) * 4 + (h2 >> 5)] = W2[i];
    }
    if (i < H_DIM * A_DIM) {
        int p = i >> 4, a = i & 15;
        int h2 = (p >> 2) + 32 * (p & 3);
        g_W3p[p * A_DIM + a] = W3[a * H_DIM + h2];
    }
}

// ---------------- gemm: cur1 = X @ W1^T + b1 (R13/R8, at fp32 floor) -------
#define GM_M      64
#define GM_THR    128
#define XS_STRIDE 132
#define GEMM_SMEM ((F_DIM * H_DIM + GM_M * XS_STRIDE) * 4)   // 97.3 KB

__global__ __launch_bounds__(GM_THR, 2)
void gemm_kernel(const float* __restrict__ state, const float* __restrict__ b1)
{
    extern __shared__ float sg[];
    float* w1t_s = sg;                          // [k][n] 128x128
    float* x_s   = sg + F_DIM * H_DIM;          // [m][k] 64x132

    const int tid  = threadIdx.x;
    const int lane = tid & 31;
    const int wrp  = tid >> 5;                  // 0..3
    const int m0   = blockIdx.x * GM_M;
    const int n0   = wrp * 32;

    #pragma unroll 8
    for (int i = tid; i < (F_DIM * H_DIM) / 4; i += GM_THR)
        reinterpret_cast<float4*>(w1t_s)[i] =
            reinterpret_cast<const float4*>(g_W1T)[i];
    #pragma unroll 4
    for (int i = tid; i < GM_M * 32; i += GM_THR) {
        int m = i >> 5, k4 = i & 31;
        float4 v = reinterpret_cast<const float4*>(state)[(size_t)(m0 + m) * 32 + k4];
        *reinterpret_cast<float4*>(&x_s[m * XS_STRIDE + 4 * k4]) = v;
    }
    __syncthreads();

    unsigned long long A0[16], A1[16];
    #pragma unroll
    for (int p = 0; p < 16; ++p) { A0[p] = 0ull; A1[p] = 0ull; }

    const float* xr0 = &x_s[lane * XS_STRIDE];
    const float* xr1 = &x_s[(lane + 32) * XS_STRIDE];

    #pragma unroll 2
    for (int k = 0; k < F_DIM; k += 4) {
        float4 xa = *reinterpret_cast<const float4*>(&xr0[k]);
        float4 xb = *reinterpret_cast<const float4*>(&xr1[k]);
        float xav[4] = {xa.x, xa.y, xa.z, xa.w};
        float xbv[4] = {xb.x, xb.y, xb.z, xb.w};
        #pragma unroll
        for (int j = 0; j < 4; ++j) {
            unsigned long long px0, px1;
            asm("mov.b64 %0, {%1, %1};" : "=l"(px0) : "f"(xav[j]));
            asm("mov.b64 %0, {%1, %1};" : "=l"(px1) : "f"(xbv[j]));
            const ulonglong2* wp =
                reinterpret_cast<const ulonglong2*>(&w1t_s[(k + j) * H_DIM + n0]);
            #pragma unroll
            for (int q = 0; q < 8; ++q) {
                ulonglong2 w2 = wp[q];
                asm("fma.rn.f32x2 %0, %1, %2, %0;" : "+l"(A0[2*q  ]) : "l"(px0), "l"(w2.x));
                asm("fma.rn.f32x2 %0, %1, %2, %0;" : "+l"(A0[2*q+1]) : "l"(px0), "l"(w2.y));
                asm("fma.rn.f32x2 %0, %1, %2, %0;" : "+l"(A1[2*q  ]) : "l"(px1), "l"(w2.x));
                asm("fma.rn.f32x2 %0, %1, %2, %0;" : "+l"(A1[2*q+1]) : "l"(px1), "l"(w2.y));
            }
        }
    }

    float bn[32];
    #pragma unroll
    for (int j = 0; j < 32; ++j) bn[j] = b1[n0 + j];

    #pragma unroll
    for (int mi = 0; mi < 2; ++mi) {
        const unsigned long long* ap = mi ? A1 : A0;
        size_t mg = (size_t)(m0 + lane + 32 * mi);
        #pragma unroll
        for (int q2 = 0; q2 < 8; ++q2) {
            float f0, f1, f2, f3;
            asm("mov.b64 {%0, %1}, %2;" : "=f"(f0), "=f"(f1) : "l"(ap[2*q2]));
            asm("mov.b64 {%0, %1}, %2;" : "=f"(f2), "=f"(f3) : "l"(ap[2*q2+1]));
            float4 o;
            o.x = __fadd_rn(f0, bn[4*q2+0]);
            o.y = __fadd_rn(f1, bn[4*q2+1]);
            o.z = __fadd_rn(f2, bn[4*q2+2]);
            o.w = __fadd_rn(f3, bn[4*q2+3]);
            reinterpret_cast<float4*>(g_cur1)[mg * 32 + (n0 >> 2) + q2] = o;
        }
    }
}

// ---------------- lif1: 65536 scalar scans, depth-4 prefetch pipeline -------
__global__ __launch_bounds__(256, 4)
void lif1_kernel(const float* __restrict__ hidden, const float* __restrict__ beta1)
{
    const int lane = threadIdx.x & 31;
    const int wg   = blockIdx.x * 8 + (threadIdx.x >> 5);
    const int b    = wg >> 2, g = wg & 3;
    const int h    = g * 32 + lane;

    const float beta = fminf(fmaxf(beta1[h], 0.0f), 1.0f);
    float mem = hidden[(size_t)b * 2 * H_DIM + h];
    const float* cb = g_cur1 + (size_t)b * T_STEPS * H_DIM + h;
    unsigned* mout = reinterpret_cast<unsigned*>(g_m1) + (size_t)b * T_STEPS * 4 + g;

    // rotating 4-slot buffer of 8-step blocks; slot index compile-time const
    float buf[4][8];
    #pragma unroll
    for (int blk = 0; blk < 3; ++blk)
        #pragma unroll
        for (int i = 0; i < 8; ++i)
            buf[blk][i] = cb[(size_t)(blk * 8 + i) * H_DIM];

    for (int o = 0; o < T_STEPS / 32; ++o) {           // 32 outer iterations
        #pragma unroll
        for (int q = 0; q < 4; ++q) {
            const int j  = o * 4 + q;                  // 8-step block index
            const int pf = j + 3;
            if (pf < T_STEPS / 8) {                    // prefetch block j+3
                #pragma unroll
                for (int i = 0; i < 8; ++i)
                    buf[(q + 3) & 3][i] = cb[(size_t)(pf * 8 + i) * H_DIM];
            }
            #pragma unroll
            for (int u = 0; u < 8; ++u) {
                float reset = (mem > 1.0f) ? 1.0f : 0.0f;
                float m = __fsub_rn(__fadd_rn(__fmul_rn(beta, mem), buf[q & 3][u]),
                                    reset);
                mem = m;
                unsigned msk = __ballot_sync(0xFFFFFFFFu, m > 1.0f);
                if (lane == 0) mout[(size_t)(j * 8 + u) * 4] = msk;
            }
        }
    }
}

// ---------------- cur2: sparse gather per (b,t), full chip ----------------
#define C2_SMEM (H_DIM * H_DIM * 4)   // 64 KB

__global__ __launch_bounds__(256, 3)
void cur2_kernel(const float* __restrict__ b2)
{
    extern __shared__ float w2s[];
    const int tid  = threadIdx.x;
    const int lane = tid & 31;

    #pragma unroll 4
    for (int i = tid; i < (H_DIM * H_DIM) / 4; i += 256)
        reinterpret_cast<float4*>(w2s)[i] =
            reinterpret_cast<const float4*>(g_W2p)[i];

    float b2j[4];
    #pragma unroll
    for (int j = 0; j < 4; ++j) b2j[j] = b2[lane + 32 * j];
    __syncthreads();

    const int W  = blockIdx.x * 8 + (tid >> 5);
    const int b  = W >> 6;
    const int t0 = (W & 63) * 16;
    const size_t base = (size_t)b * T_STEPS + t0;

    uint4 mk = g_m1[base];
    #pragma unroll 2
    for (int tt = 0; tt < 16; ++tt) {
        uint4 nk = (tt + 1 < 16) ? g_m1[base + tt + 1] : make_uint4(0u,0u,0u,0u);

        float c0 = 0.f, c1 = 0.f, c2 = 0.f, c3 = 0.f;
        unsigned mw[4] = {mk.x, mk.y, mk.z, mk.w};
        #pragma unroll
        for (int kw = 0; kw < 4; ++kw) {
            unsigned m = mw[kw];
            while (m) {
                int j = __ffs(m) - 1;
                m &= m - 1;
                float4 v = *reinterpret_cast<const float4*>(
                    &w2s[(kw * 32 + j) * H_DIM + lane * 4]);
                c0 = __fadd_rn(c0, v.x);
                c1 = __fadd_rn(c1, v.y);
                c2 = __fadd_rn(c2, v.z);
                c3 = __fadd_rn(c3, v.w);
            }
        }
        float4 o;
        o.x = __fadd_rn(c0, b2j[0]);
        o.y = __fadd_rn(c1, b2j[1]);
        o.z = __fadd_rn(c2, b2j[2]);
        o.w = __fadd_rn(c3, b2j[3]);
        reinterpret_cast<float4*>(g_cur2)[(base + tt) * 32 + lane] = o;
        mk = nk;
    }
}

// ---------------- lif2 + out fused: deep-prefetch scan, then gather --------
__global__ __launch_bounds__(256, 2)
void lif2out_kernel(const float* __restrict__ hidden,
                    const float* __restrict__ beta2,
                    const float* __restrict__ b3,
                    float* __restrict__ out)
{
    __shared__ uint4 msks[2 * T_STEPS];        // 32 KB
    __shared__ float w3s[H_DIM * A_DIM];       // 8 KB

    const int tid  = threadIdx.x;
    const int lane = tid & 31;
    const int wid  = tid >> 5;                 // 0..7

    for (int i = tid; i < H_DIM * A_DIM; i += 256) w3s[i] = g_W3p[i];

    // ---- scan phase: warp = (b_local, quarter w) ----
    const int bl = wid >> 2, w = wid & 3;
    const int b  = blockIdx.x * 2 + bl;
    const int p  = w * 32 + lane;
    const int h2 = (p >> 2) + 32 * (p & 3);

    const float beta = fminf(fmaxf(beta2[h2], 0.0f), 1.0f);
    float mem = hidden[(size_t)b * 2 * H_DIM + H_DIM + h2];
    const float* cb = g_cur2 + (size_t)b * T_STEPS * H_DIM + p;
    unsigned* mout = reinterpret_cast<unsigned*>(msks) + (size_t)bl * T_STEPS * 4 + w;

    float buf[4][8];
    #pragma unroll
    for (int blk = 0; blk < 3; ++blk)
        #pragma unroll
        for (int i = 0; i < 8; ++i)
            buf[blk][i] = cb[(size_t)(blk * 8 + i) * H_DIM];

    for (int o = 0; o < T_STEPS / 32; ++o) {
        #pragma unroll
        for (int q = 0; q < 4; ++q) {
            const int j  = o * 4 + q;
            const int pf = j + 3;
            if (pf < T_STEPS / 8) {
                #pragma unroll
                for (int i = 0; i < 8; ++i)
                    buf[(q + 3) & 3][i] = cb[(size_t)(pf * 8 + i) * H_DIM];
            }
            #pragma unroll
            for (int u = 0; u < 8; ++u) {
                float reset = (mem > 1.0f) ? 1.0f : 0.0f;
                float m = __fsub_rn(__fadd_rn(__fmul_rn(beta, mem), buf[q & 3][u]),
                                    reset);
                mem = m;
                unsigned msk = __ballot_sync(0xFFFFFFFFu, m > 1.0f);
                if (lane == 0) mout[(j * 8 + u) * 4] = msk;
            }
        }
    }

    __syncthreads();

    // ---- out phase: 2048 tasks (2 b x 1024 t), 2 per warp per pass ----
    const int a = lane & 15;
    const float b3a = b3[a];

    for (int pass = 0; pass < 128; ++pass) {
        const int task = pass * 16 + wid * 2 + (lane >> 4);
        const int tb = task >> 10;
        const int tt = task & 1023;

        uint4 mk = msks[tb * T_STEPS + tt];
        float o = 0.f;
        unsigned mw[4] = {mk.x, mk.y, mk.z, mk.w};
        #pragma unroll
        for (int kw = 0; kw < 4; ++kw) {
            unsigned m = mw[kw];
            while (m) {
                int j = __ffs(m) - 1;
                m &= m - 1;
                o = __fadd_rn(o, w3s[(kw * 32 + j) * A_DIM + a]);
            }
        }
        o = __fadd_rn(o, b3a);
        out[((size_t)(blockIdx.x * 2 + tb) * T_STEPS + tt) * A_DIM + a] = o;
    }
}

extern "C" void kernel_launch(void* const* d_in, const int* in_sizes, int n_in,
                              void* d_out, int out_size) {
    const float* state  = (const float*)d_in[0];  // [512,1024,128]
    const float* hidden = (const float*)d_in[1];  // [512,1,2,128]
    const float* W1     = (const float*)d_in[2];
    const float* b1     = (const float*)d_in[3];
    const float* beta1  = (const float*)d_in[4];
    const float* W2     = (const float*)d_in[5];
    const float* b2     = (const float*)d_in[6];
    const float* beta2  = (const float*)d_in[7];
    const float* W3     = (const float*)d_in[8];
    const float* b3     = (const float*)d_in[9];
    float* out = (float*)d_out;                   // [512,1024,16]

    cudaFuncSetAttribute(gemm_kernel,
                         cudaFuncAttributeMaxDynamicSharedMemorySize, GEMM_SMEM);
    cudaFuncSetAttribute(cur2_kernel,
                         cudaFuncAttributeMaxDynamicSharedMemorySize, C2_SMEM);

    prep_kernel<<<64, 256>>>(W1, W2, W3);
    gemm_kernel<<<M_TOT / GM_M, GM_THR, GEMM_SMEM>>>(state, b1);
    lif1_kernel<<<256, 256>>>(hidden, beta1);
    cur2_kernel<<<4096, 256, C2_SMEM>>>(b2);
    lif2out_kernel<<<256, 256>>>(hidden, beta2, b3, out);
}